// round 1
// baseline (speedup 1.0000x reference)
#include <cuda_runtime.h>
#include <cuda_bf16.h>
#include <cstdint>

#define NROWS 16384
#define DDIM  128
#define GRID_TILES 128           // NROWS / 128

// ---------------- device scratch (no allocation allowed) ----------------
__device__ __nv_bfloat16 g_An[NROWS * DDIM];
__device__ __nv_bfloat16 g_Bn[NROWS * DDIM];
__device__ float         g_partials[GRID_TILES * GRID_TILES];
__device__ int           g_is64;

// ---------------- helpers ----------------
__device__ __forceinline__ unsigned smem_u32(const void* p) {
    unsigned r;
    asm("{ .reg .u64 t; cvta.to.shared.u64 t, %1; cvt.u32.u64 %0, t; }"
        : "=r"(r) : "l"(p));
    return r;
}
// 256-byte rows (128 bf16). Swizzle 16B chunks by row%8 for conflict-free ldmatrix.
__device__ __forceinline__ unsigned swz(unsigned off) {
    return off ^ (((off >> 8) & 7u) << 4);
}

// ---------------- label dtype sniffer ----------------
__global__ void detect_kernel(const long long* __restrict__ lab) {
    int ok = 1;
    for (int i = threadIdx.x; i < NROWS; i += 256) {
        long long v = lab[i];
        if (v < 0 || v > 1000000) ok = 0;   // int32 data seen as int64 -> >= 2^32
    }
    int all = __syncthreads_and(ok);
    if (threadIdx.x == 0) g_is64 = all;
}

// ---------------- row L2 normalize -> bf16 ----------------
__global__ void norm_kernel(const float* __restrict__ in, int which) {
    int row  = blockIdx.x * 8 + (threadIdx.x >> 5);
    int lane = threadIdx.x & 31;
    float4 v = reinterpret_cast<const float4*>(in + (size_t)row * DDIM)[lane];
    float s = v.x * v.x + v.y * v.y + v.z * v.z + v.w * v.w;
    #pragma unroll
    for (int o = 16; o; o >>= 1) s += __shfl_xor_sync(0xffffffffu, s, o);
    float nrm = fmaxf(sqrtf(s), 1e-12f);
    float inv = 1.0f / nrm;
    __nv_bfloat16* dst = (which ? g_Bn : g_An) + (size_t)row * DDIM + lane * 4;
    __nv_bfloat162 p0 = __floats2bfloat162_rn(v.x * inv, v.y * inv);
    __nv_bfloat162 p1 = __floats2bfloat162_rn(v.z * inv, v.w * inv);
    reinterpret_cast<__nv_bfloat162*>(dst)[0] = p0;
    reinterpret_cast<__nv_bfloat162*>(dst)[1] = p1;
}

// ---------------- fused GEMM + exp + mask + partial reduce ----------------
// 128x128 tile per block, 256 threads = 8 warps (4 in M x 2 in N),
// warp tile 32x64, mma.sync m16n8k16 bf16, K=128 resident in smem.
__global__ void __launch_bounds__(256, 2)
loss_kernel(const long long* __restrict__ lab) {
    extern __shared__ __align__(16) unsigned char smraw[];
    __nv_bfloat16* As = reinterpret_cast<__nv_bfloat16*>(smraw);             // 128x128 bf16, 32KB
    __nv_bfloat16* Bs = As + 128 * 128;                                      // 32KB
    __shared__ int slr[128];
    __shared__ int slc[128];
    __shared__ float wsum[8];

    const int tid  = threadIdx.x;
    const int rowT = blockIdx.y;   // A tile
    const int colT = blockIdx.x;   // B tile

    // --- labels (handle int64 or int32 payload) ---
    const bool is64 = (g_is64 != 0);
    const int* lab32 = reinterpret_cast<const int*>(lab);
    if (tid < 128) {
        int i = rowT * 128 + tid;
        slr[tid] = is64 ? (int)lab[i] : lab32[i];
    } else {
        int t = tid - 128;
        int i = colT * 128 + t;
        slc[t] = is64 ? (int)lab[i] : lab32[i];
    }

    // --- load tiles (coalesced 16B), swizzled store ---
    const __nv_bfloat16* Ag = g_An + (size_t)rowT * 128 * DDIM;
    const __nv_bfloat16* Bg = g_Bn + (size_t)colT * 128 * DDIM;
    char* Ab = reinterpret_cast<char*>(As);
    char* Bb = reinterpret_cast<char*>(Bs);
    #pragma unroll
    for (int it = 0; it < 8; it++) {
        int i = tid + it * 256;            // 2048 chunks of 16B
        int r = i >> 4, c = i & 15;
        uint4 da = reinterpret_cast<const uint4*>(Ag + r * 128)[c];
        uint4 db = reinterpret_cast<const uint4*>(Bg + r * 128)[c];
        unsigned off = swz((unsigned)(r * 256 + c * 16));
        *reinterpret_cast<uint4*>(Ab + off) = da;
        *reinterpret_cast<uint4*>(Bb + off) = db;
    }
    __syncthreads();

    const int wid  = tid >> 5;
    const int lane = tid & 31;
    const int wm = (wid & 3) * 32;     // warp row base
    const int wn = (wid >> 2) * 64;    // warp col base
    const unsigned sA = smem_u32(As);
    const unsigned sB = smem_u32(Bs);

    float acc[2][8][4];
    #pragma unroll
    for (int mi = 0; mi < 2; mi++)
        #pragma unroll
        for (int ni = 0; ni < 8; ni++)
            #pragma unroll
            for (int r = 0; r < 4; r++) acc[mi][ni][r] = 0.f;

    #pragma unroll
    for (int kk = 0; kk < 8; kk++) {
        unsigned a[2][4];
        #pragma unroll
        for (int mi = 0; mi < 2; mi++) {
            int r = wm + mi * 16 + (lane & 15);
            int c16 = kk * 2 + (lane >> 4);
            unsigned addr = sA + swz((unsigned)(r * 256 + c16 * 16));
            asm volatile("ldmatrix.sync.aligned.m8n8.x4.shared.b16 {%0,%1,%2,%3}, [%4];"
                         : "=r"(a[mi][0]), "=r"(a[mi][1]), "=r"(a[mi][2]), "=r"(a[mi][3])
                         : "r"(addr));
        }
        unsigned b[8][2];
        #pragma unroll
        for (int nj = 0; nj < 4; nj++) {
            int r = wn + nj * 16 + (lane & 15);
            int c16 = kk * 2 + (lane >> 4);
            unsigned addr = sB + swz((unsigned)(r * 256 + c16 * 16));
            unsigned q0, q1, q2, q3;
            asm volatile("ldmatrix.sync.aligned.m8n8.x4.shared.b16 {%0,%1,%2,%3}, [%4];"
                         : "=r"(q0), "=r"(q1), "=r"(q2), "=r"(q3) : "r"(addr));
            b[2 * nj][0] = q0; b[2 * nj][1] = q2;
            b[2 * nj + 1][0] = q1; b[2 * nj + 1][1] = q3;
        }
        #pragma unroll
        for (int mi = 0; mi < 2; mi++)
            #pragma unroll
            for (int ni = 0; ni < 8; ni++)
                asm volatile(
                    "mma.sync.aligned.m16n8k16.row.col.f32.bf16.bf16.f32 "
                    "{%0,%1,%2,%3}, {%4,%5,%6,%7}, {%8,%9}, {%0,%1,%2,%3};"
                    : "+f"(acc[mi][ni][0]), "+f"(acc[mi][ni][1]),
                      "+f"(acc[mi][ni][2]), "+f"(acc[mi][ni][3])
                    : "r"(a[mi][0]), "r"(a[mi][1]), "r"(a[mi][2]), "r"(a[mi][3]),
                      "r"(b[ni][0]), "r"(b[ni][1]));
    }

    // --- epilogue: exp(-2*sim) where labels differ, thread-local sum ---
    float tsum = 0.f;
    #pragma unroll
    for (int mi = 0; mi < 2; mi++) {
        #pragma unroll
        for (int r = 0; r < 4; r++) {
            int row = wm + mi * 16 + (lane >> 2) + (r >> 1) * 8;
            int lr = slr[row];
            #pragma unroll
            for (int ni = 0; ni < 8; ni++) {
                int col = wn + ni * 8 + (lane & 3) * 2 + (r & 1);
                if (lr != slc[col]) tsum += __expf(-2.0f * acc[mi][ni][r]);
            }
        }
    }
    #pragma unroll
    for (int o = 16; o; o >>= 1) tsum += __shfl_xor_sync(0xffffffffu, tsum, o);
    if (lane == 0) wsum[wid] = tsum;
    __syncthreads();
    if (tid == 0) {
        float s = 0.f;
        #pragma unroll
        for (int i = 0; i < 8; i++) s += wsum[i];
        g_partials[blockIdx.y * gridDim.x + blockIdx.x] = s;
    }
}

// ---------------- deterministic final reduce ----------------
__global__ void reduce_kernel(float* __restrict__ out) {
    float s = 0.f;
    for (int i = threadIdx.x; i < GRID_TILES * GRID_TILES; i += 256) s += g_partials[i];
    #pragma unroll
    for (int o = 16; o; o >>= 1) s += __shfl_xor_sync(0xffffffffu, s, o);
    __shared__ float ws[8];
    if ((threadIdx.x & 31) == 0) ws[threadIdx.x >> 5] = s;
    __syncthreads();
    if (threadIdx.x == 0) {
        float t = 0.f;
        #pragma unroll
        for (int i = 0; i < 8; i++) t += ws[i];
        out[0] = (float)((double)t / ((double)NROWS * (double)(NROWS - 1)));
    }
}

// ---------------- launch ----------------
extern "C" void kernel_launch(void* const* d_in, const int* in_sizes, int n_in,
                              void* d_out, int out_size) {
    const float*     a   = (const float*)d_in[0];
    const float*     b   = (const float*)d_in[1];
    const long long* lab = (const long long*)d_in[2];

    detect_kernel<<<1, 256>>>(lab);
    norm_kernel<<<NROWS / 8, 256>>>(a, 0);
    norm_kernel<<<NROWS / 8, 256>>>(b, 1);

    const int smem = 128 * 128 * 2 * 2;  // 64KB dynamic
    cudaFuncSetAttribute(loss_kernel, cudaFuncAttributeMaxDynamicSharedMemorySize, smem);
    dim3 grid(GRID_TILES, GRID_TILES);
    loss_kernel<<<grid, 256, smem>>>(lab);

    reduce_kernel<<<1, 256>>>((float*)d_out);
}

// round 6
// speedup vs baseline: 1.2986x; 1.2986x over previous
#include <cuda_runtime.h>
#include <cuda_bf16.h>
#include <cstdint>

#define NROWS 16384
#define DDIM  128

// exp(-sim/T) with T=0.5 => exp(-2*sim) = 2^(sim * -2*log2(e))
#define EXP_SCALE (-2.8853900817779268f)

// ---------------- device scratch (no allocation allowed) ----------------
__device__ unsigned char g_An[NROWS * DDIM];   // e4m3
__device__ unsigned char g_Bn[NROWS * DDIM];   // e4m3
__device__ float         g_partials[128 * 128];
__device__ int           g_is64;

// ---------------- helpers ----------------
__device__ __forceinline__ unsigned smem_u32(const void* p) {
    unsigned r;
    asm("{ .reg .u64 t; cvta.to.shared.u64 t, %1; cvt.u32.u64 %0, t; }" : "=r"(r) : "l"(p));
    return r;
}
__device__ __forceinline__ float fast_ex2(float x) {
    float r;
    asm("ex2.approx.ftz.f32 %0, %1;" : "=f"(r) : "f"(x));
    return r;
}
// 128-byte rows (128 e4m3). Swizzle 16B chunks by row%8 for conflict-free ldmatrix.
__device__ __forceinline__ unsigned swz(unsigned off) {
    return off ^ ((off >> 3) & 0x70u);
}
#define CP_ASYNC16(dst, src) \
    asm volatile("cp.async.cg.shared.global [%0], [%1], 16;" :: "r"(dst), "l"(src) : "memory")
#define CP_COMMIT()  asm volatile("cp.async.commit_group;" ::: "memory")
#define CP_WAIT0()   asm volatile("cp.async.wait_group 0;" ::: "memory")

// ---------------- label dtype sniffer ----------------
__global__ void detect_kernel(const long long* __restrict__ lab) {
    int ok = 1;
    for (int i = threadIdx.x; i < NROWS; i += 256) {
        long long v = lab[i];
        if (v < 0 || v > 1000000) ok = 0;   // int32 payload seen as int64 -> huge
    }
    int all = __syncthreads_and(ok);
    if (threadIdx.x == 0) g_is64 = all;
}

// ---------------- row L2 normalize -> e4m3 ----------------
__global__ void norm_kernel(const float* __restrict__ in, int which) {
    int row  = blockIdx.x * 8 + (threadIdx.x >> 5);
    int lane = threadIdx.x & 31;
    float4 v = reinterpret_cast<const float4*>(in + (size_t)row * DDIM)[lane];
    float s = v.x * v.x + v.y * v.y + v.z * v.z + v.w * v.w;
    #pragma unroll
    for (int o = 16; o; o >>= 1) s += __shfl_xor_sync(0xffffffffu, s, o);
    float inv = 1.0f / fmaxf(sqrtf(s), 1e-12f);
    // pack 4 e4m3: byte0=v.x ... byte3=v.w (PTX cvt: first f32 source -> HIGH byte)
    unsigned short p0, p1;
    asm("cvt.rn.satfinite.e4m3x2.f32 %0, %1, %2;" : "=h"(p0) : "f"(v.y * inv), "f"(v.x * inv));
    asm("cvt.rn.satfinite.e4m3x2.f32 %0, %1, %2;" : "=h"(p1) : "f"(v.w * inv), "f"(v.z * inv));
    unsigned u = (unsigned)p0 | ((unsigned)p1 << 16);
    unsigned char* dst = (which ? g_Bn : g_An) + (size_t)row * DDIM + lane * 4;
    *reinterpret_cast<unsigned*>(dst) = u;
}

// ---------------- fused FP8 GEMM + exp + mask + partial reduce ----------------
// 128x128 tile per block, 256 threads = 8 warps (4 in M x 2 in N),
// warp tile 32x64, mma.sync m16n8k32 e4m3, K=128 resident in smem.
__global__ void __launch_bounds__(256, 2)
loss_kernel(const long long* __restrict__ lab) {
    extern __shared__ __align__(128) unsigned char smraw[];
    unsigned char* As = smraw;              // 128x128 e4m3, 16KB (swizzled)
    unsigned char* Bs = smraw + 16384;      // 16KB
    __shared__ int   slr[128], slc[128];
    __shared__ float wsum[8];

    const int tid  = threadIdx.x;
    const int rowT = blockIdx.y;   // A tile
    const int colT = blockIdx.x;   // B tile

    // --- async tile loads into swizzled smem (16B chunks) ---
    const unsigned char* Ag = g_An + (size_t)rowT * 128 * DDIM;
    const unsigned char* Bg = g_Bn + (size_t)colT * 128 * DDIM;
    const unsigned sA = smem_u32(As);
    const unsigned sB = smem_u32(Bs);
    #pragma unroll
    for (int it = 0; it < 4; it++) {
        int i = tid + it * 256;            // 1024 chunks of 16B per tile
        int r = i >> 3, c = i & 7;
        unsigned off = swz((unsigned)(r * 128 + c * 16));
        CP_ASYNC16(sA + off, Ag + r * 128 + c * 16);
        CP_ASYNC16(sB + off, Bg + r * 128 + c * 16);
    }
    CP_COMMIT();

    // --- labels while loads are in flight (int64 or int32 payload) ---
    const bool is64 = (g_is64 != 0);
    const int* lab32 = reinterpret_cast<const int*>(lab);
    if (tid < 128) {
        int i = rowT * 128 + tid;
        slr[tid] = is64 ? (int)lab[i] : lab32[i];
    } else {
        int t = tid - 128;
        int i = colT * 128 + t;
        slc[t] = is64 ? (int)lab[i] : lab32[i];
    }

    CP_WAIT0();
    __syncthreads();

    const int wid  = tid >> 5;
    const int lane = tid & 31;
    const int wm = (wid & 3) * 32;     // warp row base
    const int wn = (wid >> 2) * 64;    // warp col base

    float acc[2][8][4];
    #pragma unroll
    for (int mi = 0; mi < 2; mi++)
        #pragma unroll
        for (int ni = 0; ni < 8; ni++)
            #pragma unroll
            for (int r = 0; r < 4; r++) acc[mi][ni][r] = 0.f;

    // K = 128 e4m3 = 4 chunks of k32 (32 bytes each = two 16B chunks)
    #pragma unroll
    for (int kk = 0; kk < 4; kk++) {
        const int c16 = kk * 2 + (lane >> 4);      // 16B chunk index (0..7)
        unsigned a[2][4];
        #pragma unroll
        for (int mi = 0; mi < 2; mi++) {
            int r = wm + mi * 16 + (lane & 15);
            unsigned addr = sA + swz((unsigned)(r * 128 + c16 * 16));
            asm volatile("ldmatrix.sync.aligned.m8n8.x4.shared.b16 {%0,%1,%2,%3}, [%4];"
                         : "=r"(a[mi][0]), "=r"(a[mi][1]), "=r"(a[mi][2]), "=r"(a[mi][3])
                         : "r"(addr));
        }
        unsigned b[8][2];
        #pragma unroll
        for (int nj = 0; nj < 4; nj++) {
            int r = wn + nj * 16 + (lane & 15);
            unsigned addr = sB + swz((unsigned)(r * 128 + c16 * 16));
            unsigned q0, q1, q2, q3;
            asm volatile("ldmatrix.sync.aligned.m8n8.x4.shared.b16 {%0,%1,%2,%3}, [%4];"
                         : "=r"(q0), "=r"(q1), "=r"(q2), "=r"(q3) : "r"(addr));
            b[2 * nj][0] = q0; b[2 * nj][1] = q2;
            b[2 * nj + 1][0] = q1; b[2 * nj + 1][1] = q3;
        }
        #pragma unroll
        for (int mi = 0; mi < 2; mi++)
            #pragma unroll
            for (int ni = 0; ni < 8; ni++)
                asm volatile(
                    "mma.sync.aligned.m16n8k32.row.col.f32.e4m3.e4m3.f32 "
                    "{%0,%1,%2,%3}, {%4,%5,%6,%7}, {%8,%9}, {%0,%1,%2,%3};"
                    : "+f"(acc[mi][ni][0]), "+f"(acc[mi][ni][1]),
                      "+f"(acc[mi][ni][2]), "+f"(acc[mi][ni][3])
                    : "r"(a[mi][0]), "r"(a[mi][1]), "r"(a[mi][2]), "r"(a[mi][3]),
                      "r"(b[ni][0]), "r"(b[ni][1]));
    }

    // --- epilogue: exp(-2*sim) where labels differ ---
    // cache the 16 distinct column labels + 4 distinct row labels in regs
    int lc[16];
    #pragma unroll
    for (int ni = 0; ni < 8; ni++)
        #pragma unroll
        for (int rb = 0; rb < 2; rb++)
            lc[ni * 2 + rb] = slc[wn + ni * 8 + (lane & 3) * 2 + rb];
    int lrv[4];
    #pragma unroll
    for (int mi = 0; mi < 2; mi++)
        #pragma unroll
        for (int rh = 0; rh < 2; rh++)
            lrv[mi * 2 + rh] = slr[wm + mi * 16 + (lane >> 2) + rh * 8];

    float tsum = 0.f;
    #pragma unroll
    for (int mi = 0; mi < 2; mi++) {
        #pragma unroll
        for (int r = 0; r < 4; r++) {
            const int lr = lrv[mi * 2 + (r >> 1)];
            #pragma unroll
            for (int ni = 0; ni < 8; ni++) {
                float e = fast_ex2(acc[mi][ni][r] * EXP_SCALE);
                if (lr != lc[ni * 2 + (r & 1)]) tsum += e;
            }
        }
    }
    #pragma unroll
    for (int o = 16; o; o >>= 1) tsum += __shfl_xor_sync(0xffffffffu, tsum, o);
    if (lane == 0) wsum[wid] = tsum;
    __syncthreads();
    if (tid == 0) {
        float s = 0.f;
        #pragma unroll
        for (int i = 0; i < 8; i++) s += wsum[i];
        g_partials[blockIdx.y * gridDim.x + blockIdx.x] = s;
    }
}

// ---------------- deterministic final reduce ----------------
__global__ void reduce_kernel(float* __restrict__ out) {
    float s = 0.f;
    for (int i = threadIdx.x; i < 128 * 128; i += 256) s += g_partials[i];
    #pragma unroll
    for (int o = 16; o; o >>= 1) s += __shfl_xor_sync(0xffffffffu, s, o);
    __shared__ float ws[8];
    if ((threadIdx.x & 31) == 0) ws[threadIdx.x >> 5] = s;
    __syncthreads();
    if (threadIdx.x == 0) {
        float t = 0.f;
        #pragma unroll
        for (int i = 0; i < 8; i++) t += ws[i];
        out[0] = (float)((double)t / ((double)NROWS * (double)(NROWS - 1)));
    }
}

// ---------------- launch ----------------
extern "C" void kernel_launch(void* const* d_in, const int* in_sizes, int n_in,
                              void* d_out, int out_size) {
    const float*     a   = (const float*)d_in[0];
    const float*     b   = (const float*)d_in[1];
    const long long* lab = (const long long*)d_in[2];

    detect_kernel<<<1, 256>>>(lab);
    norm_kernel<<<NROWS / 8, 256>>>(a, 0);
    norm_kernel<<<NROWS / 8, 256>>>(b, 1);

    const int smem = 2 * 16384;  // 32KB dynamic (A+B e4m3 tiles)
    cudaFuncSetAttribute(loss_kernel, cudaFuncAttributeMaxDynamicSharedMemorySize, smem);
    dim3 grid(128, 128);
    loss_kernel<<<grid, 256, smem>>>(lab);

    reduce_kernel<<<1, 256>>>((float*)d_out);
}

// round 7
// speedup vs baseline: 1.3129x; 1.0110x over previous
#include <cuda_runtime.h>
#include <cuda_bf16.h>
#include <cstdint>

#define NROWS 16384
#define DDIM  128

// exp(-sim/T) with T=0.5 => exp(-2*sim) = 2^(sim * -2*log2(e))
// The -2*log2(e) factor is folded into A's fp8 quantization.
#define EXP_SCALE (-2.8853900817779268f)

// ---------------- device scratch (no allocation allowed) ----------------
__device__ unsigned char g_An[NROWS * DDIM];   // e4m3, rows pre-scaled by EXP_SCALE
__device__ unsigned char g_Bn[NROWS * DDIM];   // e4m3, unit rows
__device__ float         g_partials[128 * 128];
__device__ int           g_is64;

// ---------------- helpers ----------------
__device__ __forceinline__ unsigned smem_u32(const void* p) {
    unsigned r;
    asm("{ .reg .u64 t; cvta.to.shared.u64 t, %1; cvt.u32.u64 %0, t; }" : "=r"(r) : "l"(p));
    return r;
}
__device__ __forceinline__ float fast_ex2(float x) {
    float r;
    asm("ex2.approx.ftz.f32 %0, %1;" : "=f"(r) : "f"(x));
    return r;
}
// 128-byte rows (128 e4m3). Swizzle 16B chunks by row%8 for conflict-free ldmatrix.
__device__ __forceinline__ unsigned swz(unsigned off) {
    return off ^ ((off >> 3) & 0x70u);
}
#define CP_ASYNC16(dst, src) \
    asm volatile("cp.async.cg.shared.global [%0], [%1], 16;" :: "r"(dst), "l"(src) : "memory")
#define CP_COMMIT()  asm volatile("cp.async.commit_group;" ::: "memory")
#define CP_WAIT0()   asm volatile("cp.async.wait_group 0;" ::: "memory")

// ---------------- label dtype sniffer ----------------
__global__ void detect_kernel(const long long* __restrict__ lab) {
    int ok = 1;
    for (int i = threadIdx.x; i < NROWS; i += 256) {
        long long v = lab[i];
        if (v < 0 || v > 1000000) ok = 0;   // int32 payload seen as int64 -> huge
    }
    int all = __syncthreads_and(ok);
    if (threadIdx.x == 0) g_is64 = all;
}

// ---------------- fused row L2 normalize -> e4m3 (A pre-scaled) ----------------
__global__ void norm_kernel(const float* __restrict__ a, const float* __restrict__ b) {
    const int which = blockIdx.y;
    const float* in = which ? b : a;
    int row  = blockIdx.x * 8 + (threadIdx.x >> 5);
    int lane = threadIdx.x & 31;
    float4 v = reinterpret_cast<const float4*>(in + (size_t)row * DDIM)[lane];
    float s = v.x * v.x + v.y * v.y + v.z * v.z + v.w * v.w;
    #pragma unroll
    for (int o = 16; o; o >>= 1) s += __shfl_xor_sync(0xffffffffu, s, o);
    float scale = which ? 1.0f : EXP_SCALE;        // fold exp arg scale into A
    float inv = scale / fmaxf(sqrtf(s), 1e-12f);
    // pack 4 e4m3: byte0=v.x ... byte3=v.w (PTX cvt: first f32 source -> HIGH byte)
    unsigned short p0, p1;
    asm("cvt.rn.satfinite.e4m3x2.f32 %0, %1, %2;" : "=h"(p0) : "f"(v.y * inv), "f"(v.x * inv));
    asm("cvt.rn.satfinite.e4m3x2.f32 %0, %1, %2;" : "=h"(p1) : "f"(v.w * inv), "f"(v.z * inv));
    unsigned u = (unsigned)p0 | ((unsigned)p1 << 16);
    unsigned char* dst = (which ? g_Bn : g_An) + (size_t)row * DDIM + lane * 4;
    *reinterpret_cast<unsigned*>(dst) = u;
}

// ---------------- fused FP8 GEMM + exp + mask + partial reduce ----------------
// 128x128 tile per block, 256 threads = 8 warps (4 in M x 2 in N),
// warp tile 32x64, mma.sync m16n8k32 e4m3, K=128 resident in smem.
__global__ void __launch_bounds__(256, 2)
loss_kernel(const long long* __restrict__ lab) {
    extern __shared__ __align__(128) unsigned char smraw[];
    unsigned char* As = smraw;              // 128x128 e4m3, 16KB (swizzled)
    unsigned char* Bs = smraw + 16384;      // 16KB
    __shared__ int   slr[128], slc[128];
    __shared__ float wsum[8];

    const int tid  = threadIdx.x;
    const int rowT = blockIdx.y;   // A tile
    const int colT = blockIdx.x;   // B tile

    // --- async tile loads into swizzled smem (16B chunks) ---
    const unsigned char* Ag = g_An + (size_t)rowT * 128 * DDIM;
    const unsigned char* Bg = g_Bn + (size_t)colT * 128 * DDIM;
    const unsigned sA = smem_u32(As);
    const unsigned sB = smem_u32(Bs);
    #pragma unroll
    for (int it = 0; it < 4; it++) {
        int i = tid + it * 256;            // 1024 chunks of 16B per tile
        int r = i >> 3, c = i & 7;
        unsigned off = swz((unsigned)(r * 128 + c * 16));
        CP_ASYNC16(sA + off, Ag + r * 128 + c * 16);
        CP_ASYNC16(sB + off, Bg + r * 128 + c * 16);
    }
    CP_COMMIT();

    // --- labels while loads are in flight (int64 or int32 payload) ---
    const bool is64 = (g_is64 != 0);
    const int* lab32 = reinterpret_cast<const int*>(lab);
    if (tid < 128) {
        int i = rowT * 128 + tid;
        slr[tid] = is64 ? (int)lab[i] : lab32[i];
    } else {
        int t = tid - 128;
        int i = colT * 128 + t;
        slc[t] = is64 ? (int)lab[i] : lab32[i];
    }

    CP_WAIT0();
    __syncthreads();

    const int wid  = tid >> 5;
    const int lane = tid & 31;
    const int wm = (wid & 3) * 32;     // warp row base
    const int wn = (wid >> 2) * 64;    // warp col base

    float acc[2][8][4];
    #pragma unroll
    for (int mi = 0; mi < 2; mi++)
        #pragma unroll
        for (int ni = 0; ni < 8; ni++)
            #pragma unroll
            for (int r = 0; r < 4; r++) acc[mi][ni][r] = 0.f;

    // K = 128 e4m3 = 4 chunks of k32 (32 bytes each = two 16B chunks)
    #pragma unroll
    for (int kk = 0; kk < 4; kk++) {
        const int c16 = kk * 2 + (lane >> 4);      // 16B chunk index (0..7)
        unsigned a[2][4];
        #pragma unroll
        for (int mi = 0; mi < 2; mi++) {
            int r = wm + mi * 16 + (lane & 15);
            unsigned addr = sA + swz((unsigned)(r * 128 + c16 * 16));
            asm volatile("ldmatrix.sync.aligned.m8n8.x4.shared.b16 {%0,%1,%2,%3}, [%4];"
                         : "=r"(a[mi][0]), "=r"(a[mi][1]), "=r"(a[mi][2]), "=r"(a[mi][3])
                         : "r"(addr));
        }
        unsigned b[8][2];
        #pragma unroll
        for (int nj = 0; nj < 4; nj++) {
            int r = wn + nj * 16 + (lane & 15);
            unsigned addr = sB + swz((unsigned)(r * 128 + c16 * 16));
            unsigned q0, q1, q2, q3;
            asm volatile("ldmatrix.sync.aligned.m8n8.x4.shared.b16 {%0,%1,%2,%3}, [%4];"
                         : "=r"(q0), "=r"(q1), "=r"(q2), "=r"(q3) : "r"(addr));
            b[2 * nj][0] = q0; b[2 * nj][1] = q2;
            b[2 * nj + 1][0] = q1; b[2 * nj + 1][1] = q3;
        }
        #pragma unroll
        for (int mi = 0; mi < 2; mi++)
            #pragma unroll
            for (int ni = 0; ni < 8; ni++)
                asm volatile(
                    "mma.sync.aligned.m16n8k32.row.col.f32.e4m3.e4m3.f32 "
                    "{%0,%1,%2,%3}, {%4,%5,%6,%7}, {%8,%9}, {%0,%1,%2,%3};"
                    : "+f"(acc[mi][ni][0]), "+f"(acc[mi][ni][1]),
                      "+f"(acc[mi][ni][2]), "+f"(acc[mi][ni][3])
                    : "r"(a[mi][0]), "r"(a[mi][1]), "r"(a[mi][2]), "r"(a[mi][3]),
                      "r"(b[ni][0]), "r"(b[ni][1]));
    }

    // --- epilogue: acc already = EXP_SCALE*sim -> e = 2^acc; mask; sum ---
    int lc[16];
    #pragma unroll
    for (int ni = 0; ni < 8; ni++)
        #pragma unroll
        for (int rb = 0; rb < 2; rb++)
            lc[ni * 2 + rb] = slc[wn + ni * 8 + (lane & 3) * 2 + rb];
    int lrv[4];
    #pragma unroll
    for (int mi = 0; mi < 2; mi++)
        #pragma unroll
        for (int rh = 0; rh < 2; rh++)
            lrv[mi * 2 + rh] = slr[wm + mi * 16 + (lane >> 2) + rh * 8];

    float tsum = 0.f;
    #pragma unroll
    for (int mi = 0; mi < 2; mi++) {
        #pragma unroll
        for (int r = 0; r < 4; r++) {
            const int lr = lrv[mi * 2 + (r >> 1)];
            #pragma unroll
            for (int ni = 0; ni < 8; ni++) {
                float e = fast_ex2(acc[mi][ni][r]);
                if (lr != lc[ni * 2 + (r & 1)]) tsum += e;
            }
        }
    }
    #pragma unroll
    for (int o = 16; o; o >>= 1) tsum += __shfl_xor_sync(0xffffffffu, tsum, o);
    if (lane == 0) wsum[wid] = tsum;
    __syncthreads();
    if (tid == 0) {
        float s = 0.f;
        #pragma unroll
        for (int i = 0; i < 8; i++) s += wsum[i];
        g_partials[blockIdx.y * gridDim.x + blockIdx.x] = s;
    }
}

// ---------------- deterministic final reduce ----------------
__global__ void reduce_kernel(float* __restrict__ out) {
    float s = 0.f;
    for (int i = threadIdx.x; i < 128 * 128; i += 256) s += g_partials[i];
    #pragma unroll
    for (int o = 16; o; o >>= 1) s += __shfl_xor_sync(0xffffffffu, s, o);
    __shared__ float ws[8];
    if ((threadIdx.x & 31) == 0) ws[threadIdx.x >> 5] = s;
    __syncthreads();
    if (threadIdx.x == 0) {
        float t = 0.f;
        #pragma unroll
        for (int i = 0; i < 8; i++) t += ws[i];
        out[0] = (float)((double)t / ((double)NROWS * (double)(NROWS - 1)));
    }
}

// ---------------- launch ----------------
extern "C" void kernel_launch(void* const* d_in, const int* in_sizes, int n_in,
                              void* d_out, int out_size) {
    const float*     a   = (const float*)d_in[0];
    const float*     b   = (const float*)d_in[1];
    const long long* lab = (const long long*)d_in[2];

    detect_kernel<<<1, 256>>>(lab);
    dim3 ngrid(NROWS / 8, 2);
    norm_kernel<<<ngrid, 256>>>(a, b);

    const int smem = 2 * 16384;  // 32KB dynamic (A+B e4m3 tiles)
    cudaFuncSetAttribute(loss_kernel, cudaFuncAttributeMaxDynamicSharedMemorySize, smem);
    dim3 grid(128, 128);
    loss_kernel<<<grid, 256, smem>>>(lab);

    reduce_kernel<<<1, 256>>>((float*)d_out);
}

// round 8
// speedup vs baseline: 1.3232x; 1.0079x over previous
#include <cuda_runtime.h>
#include <cuda_bf16.h>
#include <cstdint>

#define NROWS 16384
#define DDIM  128
#define NBLOCKS (128 * 32)   // rowT x colGroup(4 tiles each)

// exp(-sim/T) with T=0.5 => exp(-2*sim) = 2^(sim * -2*log2(e)); folded into A quant.
#define EXP_SCALE (-2.8853900817779268f)

// ---------------- device scratch (no allocation allowed) ----------------
__device__ unsigned char g_An[NROWS * DDIM];   // e4m3, rows pre-scaled by EXP_SCALE
__device__ unsigned char g_Bn[NROWS * DDIM];   // e4m3, unit rows
__device__ float         g_partials[NBLOCKS];
__device__ int           g_done = 0;

// ---------------- helpers ----------------
__device__ __forceinline__ unsigned smem_u32(const void* p) {
    unsigned r;
    asm("{ .reg .u64 t; cvta.to.shared.u64 t, %1; cvt.u32.u64 %0, t; }" : "=r"(r) : "l"(p));
    return r;
}
__device__ __forceinline__ float fast_ex2(float x) {
    float r;
    asm("ex2.approx.ftz.f32 %0, %1;" : "=f"(r) : "f"(x));
    return r;
}
// 128-byte rows (128 e4m3). Swizzle 16B chunks by row%8 for conflict-free ldmatrix.
__device__ __forceinline__ unsigned swz(unsigned off) {
    return off ^ ((off >> 3) & 0x70u);
}
#define CP_ASYNC16(dst, src) \
    asm volatile("cp.async.cg.shared.global [%0], [%1], 16;" :: "r"(dst), "l"(src) : "memory")
#define CP_COMMIT()  asm volatile("cp.async.commit_group;" ::: "memory")
#define CP_WAIT0()   asm volatile("cp.async.wait_group 0;" ::: "memory")

// ---------------- fused row L2 normalize -> e4m3 (A pre-scaled) ----------------
__global__ void norm_kernel(const float* __restrict__ a, const float* __restrict__ b) {
    const int which = blockIdx.y;
    const float* in = which ? b : a;
    int row  = blockIdx.x * 8 + (threadIdx.x >> 5);
    int lane = threadIdx.x & 31;
    float4 v = reinterpret_cast<const float4*>(in + (size_t)row * DDIM)[lane];
    float s = v.x * v.x + v.y * v.y + v.z * v.z + v.w * v.w;
    #pragma unroll
    for (int o = 16; o; o >>= 1) s += __shfl_xor_sync(0xffffffffu, s, o);
    float scale = which ? 1.0f : EXP_SCALE;
    float inv = scale / fmaxf(sqrtf(s), 1e-12f);
    unsigned short p0, p1;
    asm("cvt.rn.satfinite.e4m3x2.f32 %0, %1, %2;" : "=h"(p0) : "f"(v.y * inv), "f"(v.x * inv));
    asm("cvt.rn.satfinite.e4m3x2.f32 %0, %1, %2;" : "=h"(p1) : "f"(v.w * inv), "f"(v.z * inv));
    unsigned u = (unsigned)p0 | ((unsigned)p1 << 16);
    unsigned char* dst = (which ? g_Bn : g_An) + (size_t)row * DDIM + lane * 4;
    *reinterpret_cast<unsigned*>(dst) = u;
}

// issue async swizzled load of one 128x128 e4m3 tile (4 chunks per thread)
__device__ __forceinline__ void load_tile(const unsigned char* __restrict__ g,
                                          unsigned smbase, int tid) {
    #pragma unroll
    for (int it = 0; it < 4; it++) {
        int i = tid + it * 256;
        int r = i >> 3, c = i & 7;
        CP_ASYNC16(smbase + swz((unsigned)(r * 128 + c * 16)), g + r * 128 + c * 16);
    }
}

// ---------------- fused FP8 GEMM + exp + mask + reduce (4 tiles/block) ----------------
__global__ void __launch_bounds__(256, 2)
loss_kernel(const long long* __restrict__ lab, float* __restrict__ out) {
    extern __shared__ __align__(128) unsigned char smraw[];
    unsigned char* As = smraw;                      // 16KB
    unsigned char* Bs0 = smraw + 16384;             // 2 x 16KB double buffer
    __shared__ int   slc[2][128];
    __shared__ float wsum[8];
    __shared__ int   sdone;

    const int tid  = threadIdx.x;
    const int wid  = tid >> 5;
    const int lane = tid & 31;
    const int rowT = blockIdx.y;
    const int colG = blockIdx.x;          // 4 consecutive col tiles
    const int col0 = colG * 512;

    const unsigned sA = smem_u32(As);
    const unsigned sB0 = smem_u32(Bs0);

    // --- issue A + B0 loads immediately ---
    load_tile(g_An + (size_t)rowT * 128 * DDIM, sA, tid);
    load_tile(g_Bn + (size_t)col0 * DDIM, sB0, tid);
    CP_COMMIT();

    // --- int64 vs int32 label sniff (per-warp, no extra launch) ---
    // int32 payload read as int64 merges pairs; high half in [0,100) is ~never all-zero
    long long e0 = lab[lane], e1 = lab[32 + lane];
    int inr = (e0 >= 0 && e0 <= 1000000 && e1 >= 0 && e1 <= 1000000) ? 1 : 0;
    const bool is64 = (__all_sync(0xffffffffu, inr) != 0);
    const int* lab32 = reinterpret_cast<const int*>(lab);

    const int wm = (wid & 3) * 32;
    const int wn = (wid >> 2) * 64;

    // row labels for this thread's 4 accumulator rows (L2 hits, once per block)
    int lrv[4];
    #pragma unroll
    for (int mi = 0; mi < 2; mi++)
        #pragma unroll
        for (int rh = 0; rh < 2; rh++) {
            int r = rowT * 128 + wm + mi * 16 + (lane >> 2) + rh * 8;
            lrv[mi * 2 + rh] = is64 ? (int)lab[r] : lab32[r];
        }
    // col labels tile 0
    if (tid < 128) {
        int i = col0 + tid;
        slc[0][tid] = is64 ? (int)lab[i] : lab32[i];
    }

    float tsum = 0.f;

    #pragma unroll 1
    for (int j = 0; j < 4; j++) {
        const int cur = j & 1, nxt = cur ^ 1;
        CP_WAIT0();
        __syncthreads();

        // prefetch next B tile + its labels (overlaps MMA+epilogue below)
        if (j < 3) {
            load_tile(g_Bn + (size_t)(col0 + (j + 1) * 128) * DDIM, sB0 + nxt * 16384, tid);
            CP_COMMIT();
            if (tid < 128) {
                int i = col0 + (j + 1) * 128 + tid;
                slc[nxt][tid] = is64 ? (int)lab[i] : lab32[i];
            }
        }

        const unsigned sB = sB0 + cur * 16384;
        float acc[2][8][4];
        #pragma unroll
        for (int mi = 0; mi < 2; mi++)
            #pragma unroll
            for (int ni = 0; ni < 8; ni++)
                #pragma unroll
                for (int r = 0; r < 4; r++) acc[mi][ni][r] = 0.f;

        #pragma unroll
        for (int kk = 0; kk < 4; kk++) {
            const int c16 = kk * 2 + (lane >> 4);
            unsigned a[2][4];
            #pragma unroll
            for (int mi = 0; mi < 2; mi++) {
                int r = wm + mi * 16 + (lane & 15);
                unsigned addr = sA + swz((unsigned)(r * 128 + c16 * 16));
                asm volatile("ldmatrix.sync.aligned.m8n8.x4.shared.b16 {%0,%1,%2,%3}, [%4];"
                             : "=r"(a[mi][0]), "=r"(a[mi][1]), "=r"(a[mi][2]), "=r"(a[mi][3])
                             : "r"(addr));
            }
            unsigned b[8][2];
            #pragma unroll
            for (int nj = 0; nj < 4; nj++) {
                int r = wn + nj * 16 + (lane & 15);
                unsigned addr = sB + swz((unsigned)(r * 128 + c16 * 16));
                unsigned q0, q1, q2, q3;
                asm volatile("ldmatrix.sync.aligned.m8n8.x4.shared.b16 {%0,%1,%2,%3}, [%4];"
                             : "=r"(q0), "=r"(q1), "=r"(q2), "=r"(q3) : "r"(addr));
                b[2 * nj][0] = q0; b[2 * nj][1] = q2;
                b[2 * nj + 1][0] = q1; b[2 * nj + 1][1] = q3;
            }
            #pragma unroll
            for (int mi = 0; mi < 2; mi++)
                #pragma unroll
                for (int ni = 0; ni < 8; ni++)
                    asm volatile(
                        "mma.sync.aligned.m16n8k32.row.col.f32.e4m3.e4m3.f32 "
                        "{%0,%1,%2,%3}, {%4,%5,%6,%7}, {%8,%9}, {%0,%1,%2,%3};"
                        : "+f"(acc[mi][ni][0]), "+f"(acc[mi][ni][1]),
                          "+f"(acc[mi][ni][2]), "+f"(acc[mi][ni][3])
                        : "r"(a[mi][0]), "r"(a[mi][1]), "r"(a[mi][2]), "r"(a[mi][3]),
                          "r"(b[ni][0]), "r"(b[ni][1]));
        }

        // --- epilogue: acc = EXP_SCALE*sim -> e = 2^acc; mask; accumulate ---
        int lc[16];
        #pragma unroll
        for (int ni = 0; ni < 8; ni++)
            #pragma unroll
            for (int rb = 0; rb < 2; rb++)
                lc[ni * 2 + rb] = slc[cur][wn + ni * 8 + (lane & 3) * 2 + rb];

        #pragma unroll
        for (int mi = 0; mi < 2; mi++) {
            #pragma unroll
            for (int r = 0; r < 4; r++) {
                const int lr = lrv[mi * 2 + (r >> 1)];
                #pragma unroll
                for (int ni = 0; ni < 8; ni++) {
                    float e = fast_ex2(acc[mi][ni][r]);
                    if (lr != lc[ni * 2 + (r & 1)]) tsum += e;
                }
            }
        }
    }

    // --- block reduce (deterministic order) ---
    #pragma unroll
    for (int o = 16; o; o >>= 1) tsum += __shfl_xor_sync(0xffffffffu, tsum, o);
    if (lane == 0) wsum[wid] = tsum;
    __syncthreads();
    if (tid == 0) {
        float s = 0.f;
        #pragma unroll
        for (int i = 0; i < 8; i++) s += wsum[i];
        g_partials[blockIdx.y * gridDim.x + blockIdx.x] = s;
        __threadfence();
        sdone = atomicAdd(&g_done, 1);
    }
    __syncthreads();

    // --- last block performs the deterministic final reduction ---
    if (sdone == NBLOCKS - 1) {
        __threadfence();
        float s = 0.f;
        for (int i = tid; i < NBLOCKS; i += 256) s += g_partials[i];
        #pragma unroll
        for (int o = 16; o; o >>= 1) s += __shfl_xor_sync(0xffffffffu, s, o);
        if (lane == 0) wsum[wid] = s;
        __syncthreads();
        if (tid == 0) {
            float t = 0.f;
            #pragma unroll
            for (int i = 0; i < 8; i++) t += wsum[i];
            out[0] = (float)((double)t / ((double)NROWS * (double)(NROWS - 1)));
            g_done = 0;   // reset for next graph replay
        }
    }
}

// ---------------- launch ----------------
extern "C" void kernel_launch(void* const* d_in, const int* in_sizes, int n_in,
                              void* d_out, int out_size) {
    const float*     a   = (const float*)d_in[0];
    const float*     b   = (const float*)d_in[1];
    const long long* lab = (const long long*)d_in[2];

    dim3 ngrid(NROWS / 8, 2);
    norm_kernel<<<ngrid, 256>>>(a, b);

    const int smem = 3 * 16384;  // A + double-buffered B
    cudaFuncSetAttribute(loss_kernel, cudaFuncAttributeMaxDynamicSharedMemorySize, smem);
    dim3 grid(32, 128);
    loss_kernel<<<grid, 256, smem>>>(lab, (float*)d_out);
}